// round 13
// baseline (speedup 1.0000x reference)
#include <cuda_runtime.h>
#include <cstdint>

// Problem constants (fixed by the reference).
#define Bsz   1024
#define Lsz   32
#define Hsz   128
#define Gsz   8      // samples per CTA
#define G2sz  4      // sample pairs per CTA
#define NCTA  128    // Bsz / Gsz
#define TPB   256

// Vertical-carry scratch: [cta][g2][lattice p][layer][t] as float2 (sample pair).
// 128*4*32*2*128 float2 = 33.5 MB, L2-resident working set per CTA = 256KB.
__device__ float2 g_scr[(size_t)NCTA * G2sz * Lsz * 2 * Hsz];

static __device__ __forceinline__ unsigned long long pk2(float x, float y) {
    unsigned long long r;
    asm("mov.b64 %0, {%1, %2};" : "=l"(r) : "f"(x), "f"(y));
    return r;
}
static __device__ __forceinline__ float2 up2(unsigned long long v) {
    float2 r;
    asm("mov.b64 {%0, %1}, %2;" : "=f"(r.x), "=f"(r.y) : "l"(v));
    return r;
}
// packed fp32x2 FMA / ADD (FFMA2 in SASS — PTX-only path on sm_103a)
static __device__ __forceinline__ unsigned long long fma2(unsigned long long a,
                                                          unsigned long long b,
                                                          unsigned long long c) {
    unsigned long long d;
    asm("fma.rn.f32x2 %0, %1, %2, %3;" : "=l"(d) : "l"(a), "l"(b), "l"(c));
    return d;
}
static __device__ __forceinline__ unsigned long long add2(unsigned long long a,
                                                          unsigned long long b) {
    unsigned long long d;
    asm("add.rn.f32x2 %0, %1, %2;" : "=l"(d) : "l"(a), "l"(b));
    return d;
}
static __device__ __forceinline__ float eluf(float v) {
    return v > 0.f ? v : (__expf(v) - 1.f);
}

__global__ void __launch_bounds__(TPB, 1)
rnn2d_kernel(const int* __restrict__ x,
             const float* __restrict__ WH,
             const float* __restrict__ WV,
             const float* __restrict__ WS0,
             const float* __restrict__ WS1,
             const float* __restrict__ Wout,
             const float* __restrict__ bout,
             float* __restrict__ out)
{
    // Carry operand arrays: .x = {carryH pair}, .y = {carryV pair} packed fp32x2.
    __shared__ ulonglong2 C0s[G2sz][Hsz];         // layer-0 carries
    __shared__ ulonglong2 C1s[G2sz][Hsz];         // layer-1 carries
    __shared__ unsigned long long H0sm[G2sz][Hsz]; // current-site h0 pairs
    __shared__ unsigned long long RedS[G2sz][Hsz]; // cross-half partial sums
    __shared__ float2 OutRedS[4][G2sz];            // per-warp output-dot partials
    __shared__ float WS0s[4 * Hsz];
    __shared__ float WoutS[Hsz];
    __shared__ int xsH[Gsz], xsV[Gsz], xsC[Gsz];
    __shared__ float boutS;

    const int tid  = threadIdx.x;
    const int cta  = blockIdx.x;
    const int t    = tid & (Hsz - 1);   // output lane 0..127
    const int half = tid >> 7;          // k-range half: 0 -> k in [0,64), 1 -> [64,128)
    const int k0   = half * (Hsz / 2);

    for (int idx = tid; idx < 4 * Hsz; idx += TPB) WS0s[idx] = WS0[idx];
    for (int idx = tid; idx < Hsz; idx += TPB)     WoutS[idx] = Wout[idx];
    if (tid == 0) boutS = bout[0];

    const float* WH0 = WH;
    const float* WH1 = WH + Hsz * Hsz;
    const float* WV0 = WV;
    const float* WV1 = WV + Hsz * Hsz;

    float2* scrBase = g_scr + (size_t)cta * (G2sz * Lsz * 2 * Hsz);

    float lpAcc = 0.f;
    __syncthreads();

    for (int i = 0; i < Lsz; ++i) {
        const int d = (i & 1) ? -1 : 1;             // boustrophedon direction
        for (int j = 0; j < Lsz; ++j) {
            const int p = (d == 1) ? j : (Lsz - 1 - j);   // lattice column

            // ---------------- staging ----------------
            if (tid < Gsz) {
                const int g = tid;
                const int base = (cta * Gsz + g) * (Lsz * Lsz) + i * Lsz;
                xsC[g] = __ldg(x + base + p);
                xsH[g] = (j > 0) ? __ldg(x + base + (p - d)) : -1;
                xsV[g] = (i > 0) ? __ldg(x + base - Lsz + p) : -1;
            }
            {
                ulonglong2* Cbase = half ? &C1s[0][0] : &C0s[0][0];
#pragma unroll
                for (int g2 = 0; g2 < G2sz; ++g2) {
                    unsigned long long v = 0ull;
                    if (i > 0) {
                        const float2 f = scrBase[((g2 * Lsz + p) * 2 + half) * Hsz + t];
                        v = pk2(f.x, f.y);
                    }
                    ulonglong2* Cp = Cbase + g2 * Hsz + t;
                    Cp->y = v;                       // vertical carry
                    if (j == 0) Cp->x = 0ull;        // horizontal carry resets per row
                }
            }
            __syncthreads();   // s1

            // ---------------- layer 0 ----------------
            unsigned long long a[G2sz];
            if (half == 0) {
                // state @ WS0 = (at most) two row picks of WS0
#pragma unroll
                for (int g2 = 0; g2 < G2sz; ++g2) {
                    const int he = xsH[2 * g2],     ho = xsH[2 * g2 + 1];
                    const int ve = xsV[2 * g2],     vo = xsV[2 * g2 + 1];
                    float se = 0.f, so = 0.f;
                    if (he >= 0) se += WS0s[he * Hsz + t];
                    if (ve >= 0) se += WS0s[(2 + ve) * Hsz + t];
                    if (ho >= 0) so += WS0s[ho * Hsz + t];
                    if (vo >= 0) so += WS0s[(2 + vo) * Hsz + t];
                    a[g2] = pk2(se, so);
                }
            } else {
#pragma unroll
                for (int g2 = 0; g2 < G2sz; ++g2) a[g2] = 0ull;
            }
            {
                const float* pwh = WH0 + (size_t)k0 * Hsz + t;
                const float* pwv = WV0 + (size_t)k0 * Hsz + t;
#pragma unroll 8
                for (int kk = 0; kk < Hsz / 2; ++kk) {
                    const int k = k0 + kk;
                    const float whf = __ldg(pwh); pwh += Hsz;
                    const float wvf = __ldg(pwv); pwv += Hsz;
                    const unsigned long long wh = pk2(whf, whf);
                    const unsigned long long wv = pk2(wvf, wvf);
#pragma unroll
                    for (int g2 = 0; g2 < G2sz; ++g2) {
                        const ulonglong2 c = C0s[g2][k];   // LDS.128 broadcast
                        a[g2] = fma2(c.x, wh, a[g2]);
                        a[g2] = fma2(c.y, wv, a[g2]);
                    }
                }
            }
            if (half) {
#pragma unroll
                for (int g2 = 0; g2 < G2sz; ++g2) RedS[g2][t] = a[g2];
            }
            __syncthreads();   // s2
            if (!half) {
#pragma unroll
                for (int g2 = 0; g2 < G2sz; ++g2) {
                    float2 h = up2(add2(a[g2], RedS[g2][t]));
                    h.x = eluf(h.x); h.y = eluf(h.y);
                    const unsigned long long hu = pk2(h.x, h.y);
                    C0s[g2][t].x = hu;                                   // next-site carryH0
                    H0sm[g2][t] = hu;                                    // feeds WS1 matvec
                    scrBase[((g2 * Lsz + p) * 2 + 0) * Hsz + t] = h;     // next-row carryV0
                }
            }
            __syncthreads();   // s3

            // ---------------- layer 1 ----------------
#pragma unroll
            for (int g2 = 0; g2 < G2sz; ++g2) a[g2] = 0ull;
            {
                const float* pwh = WH1 + (size_t)k0 * Hsz + t;
                const float* pwv = WV1 + (size_t)k0 * Hsz + t;
                const float* pws = WS1 + (size_t)k0 * Hsz + t;
#pragma unroll 8
                for (int kk = 0; kk < Hsz / 2; ++kk) {
                    const int k = k0 + kk;
                    const float whf = __ldg(pwh); pwh += Hsz;
                    const float wvf = __ldg(pwv); pwv += Hsz;
                    const float wsf = __ldg(pws); pws += Hsz;
                    const unsigned long long wh = pk2(whf, whf);
                    const unsigned long long wv = pk2(wvf, wvf);
                    const unsigned long long ws = pk2(wsf, wsf);
#pragma unroll
                    for (int g2 = 0; g2 < G2sz; ++g2) {
                        const ulonglong2 c = C1s[g2][k];
                        const unsigned long long h0u = H0sm[g2][k];
                        a[g2] = fma2(c.x, wh, a[g2]);
                        a[g2] = fma2(c.y, wv, a[g2]);
                        a[g2] = fma2(h0u, ws, a[g2]);
                    }
                }
            }
            if (half) {
#pragma unroll
                for (int g2 = 0; g2 < G2sz; ++g2) RedS[g2][t] = a[g2];
            }
            __syncthreads();   // s4
            if (!half) {
                const float wof = WoutS[t];
                const unsigned long long wo = pk2(wof, wof);
#pragma unroll
                for (int g2 = 0; g2 < G2sz; ++g2) {
                    float2 h = up2(add2(a[g2], RedS[g2][t]));
                    h.x = eluf(h.x); h.y = eluf(h.y);
                    const unsigned long long hu = pk2(h.x, h.y);
                    C1s[g2][t].x = hu;                                   // next-site carryH1
                    scrBase[((g2 * Lsz + p) * 2 + 1) * Hsz + t] = h;     // next-row carryV1
                    a[g2] = fma2(hu, wo, 0ull);                          // output-dot partial
                }
                // intra-warp reduce of the output dot (pairs stay packed)
#pragma unroll
                for (int off = 16; off > 0; off >>= 1) {
#pragma unroll
                    for (int g2 = 0; g2 < G2sz; ++g2)
                        a[g2] = add2(a[g2], __shfl_down_sync(0xffffffffu, a[g2], off));
                }
                if ((tid & 31) == 0) {
#pragma unroll
                    for (int g2 = 0; g2 < G2sz; ++g2)
                        OutRedS[tid >> 5][g2] = up2(a[g2]);
                }
            }
            __syncthreads();   // s5
            if (tid < Gsz) {
                const int g = tid;
                float c = boutS;
#pragma unroll
                for (int w = 0; w < 4; ++w) {
                    const float2 v = OutRedS[w][g >> 1];
                    c += (g & 1) ? v.y : v.x;
                }
                // 0.5 * log_softmax([0, c]) picked by the observed spin
                const float sp = fmaxf(c, 0.f) + log1pf(__expf(-fabsf(c)));
                float lp = 0.5f * (((xsC[g] == 1) ? c : 0.f) - sp);
                if (!(lp == lp)) lp = -35.0f;   // nan_to_num semantics
                lpAcc += lp;
            }
        }
    }

    if (tid < Gsz) out[cta * Gsz + tid] = lpAcc;
}

extern "C" void kernel_launch(void* const* d_in, const int* in_sizes, int n_in,
                              void* d_out, int out_size) {
    const int*   x    = (const int*)d_in[0];
    const float* WH   = (const float*)d_in[1];
    const float* WV   = (const float*)d_in[2];
    const float* WS0  = (const float*)d_in[3];
    const float* WS1  = (const float*)d_in[4];
    const float* Wout = (const float*)d_in[5];
    const float* bo   = (const float*)d_in[6];
    float* out = (float*)d_out;
    rnn2d_kernel<<<NCTA, TPB>>>(x, WH, WV, WS0, WS1, Wout, bo, out);
}